// round 17
// baseline (speedup 1.0000x reference)
#include <cuda_runtime.h>
#include <cuda_fp16.h>
#include <cuda_pipeline.h>
#include <cstdint>

#define N_VEH    40000
#define N_PATHS  400000
#define N_TILES  6250
#define TILE_M   64
#define NTHREADS 256
#define VTILE    128
#define VTHREADS 512
#define XSB      336     // xbuf row stride in BYTES (168 halfs); conflict-free ldmatrix

// Per-vehicle partials [N_VEH][320]: cols 0..159 = w1_a @ va, 160..319 = wt_a @ va
__device__ float g_PV[(size_t)N_VEH * 320];
// Packed fp16 weights in m16n8k16 B-fragment order:
// [slice:5][wn:4][chunk:10][nf:5][lane:32] of uint2 {b0,b1}
// slice 0: w1[:,0:160], 1: wt[:,0:160], 2: w2, 3: w1[:,160:320], 4: wt[:,160:320]
__device__ __align__(16) uint2 g_WPK[32000];

__device__ __forceinline__ unsigned h2u(float lo, float hi) {
    __half2 h = __floats2half2_rn(lo, hi);
    return *(unsigned*)&h;
}

__device__ __forceinline__ void mma16(float* d, const unsigned* a, const unsigned* b) {
    asm volatile(
        "mma.sync.aligned.m16n8k16.row.col.f32.f16.f16.f32 "
        "{%0,%1,%2,%3}, {%4,%5,%6,%7}, {%8,%9}, {%0,%1,%2,%3};\n"
        : "+f"(d[0]), "+f"(d[1]), "+f"(d[2]), "+f"(d[3])
        : "r"(a[0]), "r"(a[1]), "r"(a[2]), "r"(a[3]), "r"(b[0]), "r"(b[1]));
}
__device__ __forceinline__ void ldsm4(unsigned a[4], uint32_t addr) {
    asm volatile("ldmatrix.sync.aligned.m8n8.x4.shared.b16 {%0,%1,%2,%3}, [%4];"
                 : "=r"(a[0]), "=r"(a[1]), "=r"(a[2]), "=r"(a[3]) : "r"(addr));
}
__device__ __forceinline__ void pref_l2(const void* p) {
    asm volatile("prefetch.global.L2 [%0];" :: "l"(p));
}

// Pack kernel: fp16 B fragments. One thread per uint2.
__global__ void pack_kernel(const float* __restrict__ w1, const float* __restrict__ w2,
                            const float* __restrict__ wt)
{
    int idx = blockIdx.x * blockDim.x + threadIdx.x;
    if (idx >= 32000) return;
    int lane = idx & 31;
    int nf   = (idx >> 5) % 5;
    int chunk= (idx / 160) % 10;
    int wn   = (idx / 1600) & 3;
    int slice= idx / 6400;

    const float* src; int gs, ko;
    switch (slice) {
        case 0: src = w1; gs = 320; ko = 0;   break;
        case 1: src = wt; gs = 320; ko = 0;   break;
        case 2: src = w2; gs = 160; ko = 0;   break;
        case 3: src = w1; gs = 320; ko = 160; break;
        default:src = wt; gs = 320; ko = 160; break;
    }
    int n = wn * 40 + nf * 8 + (lane >> 2);
    int kb = chunk * 16 + (lane & 3) * 2;
    const float* r = src + (size_t)n * gs + ko;
    uint2 o;
    o.x = h2u(r[kb],     r[kb + 1]);
    o.y = h2u(r[kb + 8], r[kb + 9]);
    g_WPK[idx] = o;
}

// Single GEMM pass (used by veh_pre): acc += X @ Wslice^T. B double-buffered from global.
__device__ __forceinline__ void gemm_pass_h(
    float acc[2][5][4],
    const uint2* __restrict__ pk, uint32_t xaddr0, int lane)
{
    const uint2* bp = pk + lane;
    uint2 b[2][5];
    #pragma unroll
    for (int j = 0; j < 5; j++) b[0][j] = __ldg(bp + j * 32);

    #pragma unroll
    for (int chunk = 0; chunk < 10; chunk++) {
        const int cur = chunk & 1;
        if (chunk < 9) {
            #pragma unroll
            for (int j = 0; j < 5; j++)
                b[cur ^ 1][j] = __ldg(bp + ((chunk + 1) * 5 + j) * 32);
        }
        unsigned a[2][4];
        uint32_t ad = xaddr0 + (uint32_t)(chunk * 32);
        ldsm4(a[0], ad);
        ldsm4(a[1], ad + 16 * XSB);
        #pragma unroll
        for (int mf = 0; mf < 2; mf++)
            #pragma unroll
            for (int nf = 0; nf < 5; nf++)
                mma16(acc[mf][nf], a[mf], &b[cur][nf].x);
    }
}

// Kernel 1: per-vehicle partial sums into g_PV (slices 3,4). One pass per blockIdx.y.
__global__ void __launch_bounds__(VTHREADS, 1)
veh_pre_kernel(const float* __restrict__ actors, const float* __restrict__ Z_act)
{
    extern __shared__ char smem[];
    char* xbuf = smem;                       // 128 * 336 bytes (fp16)
    const int tid = threadIdx.x;
    const int v0 = blockIdx.x * VTILE;
    const int pass = blockIdx.y;             // 0: slice3 -> PV[0:160], 1: slice4 -> PV[160:320]

    for (int i = tid; i < VTILE * 40; i += VTHREADS) {
        int r = i / 40, k4 = i - r * 40;
        int v = v0 + r;
        float4 x = make_float4(0.f, 0.f, 0.f, 0.f);
        if (v < N_VEH)
            x = (k4 < 32) ? __ldcg((const float4*)actors + (size_t)v * 32 + k4)
                          : __ldcg((const float4*)Z_act + (size_t)v * 8 + (k4 - 32));
        uint2 o; o.x = h2u(x.x, x.y); o.y = h2u(x.z, x.w);
        *(uint2*)(xbuf + r * XSB + k4 * 8) = o;
    }
    __syncthreads();

    const int lane = tid & 31, warp = tid >> 5;
    const int wm = warp & 3, wn = warp >> 2;
    const int qr = lane >> 2, qc = lane & 3;
    const int rb = wm * 32 + qr;
    const int cb = wn * 40 + 2 * qc;

    uint32_t xs_b = (uint32_t)__cvta_generic_to_shared(xbuf);
    uint32_t xaddr0 = xs_b + (uint32_t)((wm * 32 + (lane & 15)) * XSB + (lane >> 4) * 16);

    const int slice = 3 + pass;
    const int coloff = pass ? 160 : 0;
    float acc[2][5][4] = {};
    gemm_pass_h(acc, g_WPK + (slice * 4 + wn) * 1600, xaddr0, lane);
    #pragma unroll
    for (int mf = 0; mf < 2; mf++) {
        int r = rb + mf * 16;
        int vA = v0 + r, vB = v0 + r + 8;
        #pragma unroll
        for (int nf = 0; nf < 5; nf++) {
            int c = cb + nf * 8;
            if (vA < N_VEH)
                *(float2*)(g_PV + (size_t)vA * 320 + coloff + c) =
                    make_float2(acc[mf][nf][0], acc[mf][nf][1]);
            if (vB < N_VEH)
                *(float2*)(g_PV + (size_t)vB * 320 + coloff + c) =
                    make_float2(acc[mf][nf][2], acc[mf][nf][3]);
        }
    }
}

// Kernel 2: PERSISTENT fused per-path pipeline. 256 thr, 2 CTAs/SM, grid-stride tile loop.
// b2s staged once per CTA. Streaming traffic (x, PV) bypasses L1 (.cg) so the merged-pass
// B weights (51.2 KB, identical every tile, shared by both CTAs) stay L1-resident.
__global__ void __launch_bounds__(NTHREADS, 2)
path_main_kernel(
    const float* __restrict__ paths, const float* __restrict__ Z_pat,
    const int* __restrict__ u,
    const float* __restrict__ g1w, const float* __restrict__ g1b,
    const float* __restrict__ g2w, const float* __restrict__ g2b,
    const float* __restrict__ wh, const float* __restrict__ bh,
    float* __restrict__ out)
{
    extern __shared__ char smem[];
    char*  xbuf = smem;                              // 64*336 = 21504 B
    char*  b2s  = smem + TILE_M * XSB;               // 51200 B (slice-2 B image)
    int*   u_s  = (int*)(b2s + 51200);               // 64
    float* rsum = (float*)(u_s + TILE_M);            // 64
    float* rssq = rsum + TILE_M;
    float* rsum2= rssq + TILE_M;
    float* rssq2= rsum2 + TILE_M;
    float* oacc = rssq2 + TILE_M;
    float* p1w = oacc + TILE_M;                      // 5 x 160 params
    float* p1b = p1w + 160;
    float* p2w = p1b + 160;
    float* p2b = p2w + 160;
    float* pwh = p2b + 160;

    const int tid = threadIdx.x;
    const int lane = tid & 31, warp = tid >> 5;
    const int wm = warp & 1, wn = warp >> 1;
    const int qr = lane >> 2, qc = lane & 3;
    const int rb = wm * 32 + qr;
    const int cb = wn * 40 + 2 * qc;

    uint32_t xs_b = (uint32_t)__cvta_generic_to_shared(xbuf);
    uint32_t xaddr0 = xs_b + (uint32_t)((wm * 32 + (lane & 15)) * XSB + (lane >> 4) * 16);

    // ---- prologue (once per CTA) ----
    {
        const char* src = (const char*)(g_WPK + 2 * 6400);
        for (int off = tid * 16; off < 51200; off += NTHREADS * 16)
            __pipeline_memcpy_async(b2s + off, src + off, 16);
        __pipeline_commit();
    }
    for (int i = tid; i < 160; i += NTHREADS) {
        p1w[i] = g1w[i]; p1b[i] = g1b[i];
        p2w[i] = g2w[i]; p2b[i] = g2b[i];
        pwh[i] = wh[i];
    }
    if (tid < TILE_M) {
        rsum[tid] = 0.0f; rssq[tid] = 0.0f;
        rsum2[tid] = 0.0f; rssq2[tid] = 0.0f; oacc[tid] = 0.0f;
    }
    __pipeline_wait_prior(0);

    const float bhv = __ldg(bh);

    #pragma unroll 1
    for (int tile = blockIdx.x; tile < N_TILES; tile += gridDim.x) {
        const int row0 = tile * TILE_M;

        // ---- stage tile inputs (L1-bypassing) + PV L2 prefetch ----
        {
            int r = tid >> 2, p = tid & 3;
            int uv = __ldcg(u + row0 + r);
            const char* base = (const char*)(g_PV + (size_t)uv * 320) + p * 320;
            pref_l2(base); pref_l2(base + 128); pref_l2(base + 256);
            if (p == 0) u_s[r] = uv;
        }
        for (int i = tid; i < TILE_M * 40; i += NTHREADS) {
            int r = i / 40, k4 = i - r * 40;
            float4 x = (k4 < 32) ? __ldcg((const float4*)paths + (size_t)(row0 + r) * 32 + k4)
                                 : __ldcg((const float4*)Z_pat + (size_t)(row0 + r) * 8 + (k4 - 32));
            uint2 o; o.x = h2u(x.x, x.y); o.y = h2u(x.z, x.w);
            *(uint2*)(xbuf + r * XSB + k4 * 8) = o;
        }
        __syncthreads();

        // ---- merged pass T + 1: tacc = xp @ wt_p^T ; acc1 = xp @ w1_p^T ----
        float tacc[2][5][4] = {};
        float acc1[2][5][4] = {};
        {
            const uint2* bpT = g_WPK + (1 * 4 + wn) * 1600 + lane;  // slice 1 (wt_p)
            const uint2* bp1 = g_WPK + (0 * 4 + wn) * 1600 + lane;  // slice 0 (w1_p)
            uint2 bT[5], b1[5];
            #pragma unroll
            for (int j = 0; j < 5; j++) bT[j] = __ldg(bpT + j * 32);

            #pragma unroll
            for (int chunk = 0; chunk < 10; chunk++) {
                #pragma unroll
                for (int j = 0; j < 5; j++) b1[j] = __ldg(bp1 + (chunk * 5 + j) * 32);
                unsigned a[2][4];
                uint32_t ad = xaddr0 + (uint32_t)(chunk * 32);
                ldsm4(a[0], ad);
                ldsm4(a[1], ad + 16 * XSB);
                #pragma unroll
                for (int mf = 0; mf < 2; mf++)
                    #pragma unroll
                    for (int nf = 0; nf < 5; nf++)
                        mma16(tacc[mf][nf], a[mf], &bT[nf].x);
                if (chunk < 9) {
                    #pragma unroll
                    for (int j = 0; j < 5; j++) bT[j] = __ldg(bpT + ((chunk + 1) * 5 + j) * 32);
                }
                #pragma unroll
                for (int mf = 0; mf < 2; mf++)
                    #pragma unroll
                    for (int nf = 0; nf < 5; nf++)
                        mma16(acc1[mf][nf], a[mf], &b1[nf].x);
            }
        }

        // PV adds for both streams (L1-bypassing loads)
        #pragma unroll
        for (int mf = 0; mf < 2; mf++) {
            int r = rb + mf * 16;
            const float* pvA = g_PV + (size_t)u_s[r] * 320;
            const float* pvB = g_PV + (size_t)u_s[r + 8] * 320;
            #pragma unroll
            for (int nf = 0; nf < 5; nf++) {
                int c = cb + nf * 8;
                float2 t0 = __ldcg((const float2*)(pvA + 160 + c));
                float2 t1 = __ldcg((const float2*)(pvB + 160 + c));
                tacc[mf][nf][0] += t0.x; tacc[mf][nf][1] += t0.y;
                tacc[mf][nf][2] += t1.x; tacc[mf][nf][3] += t1.y;
                float2 h0 = __ldcg((const float2*)(pvA + c));
                float2 h1 = __ldcg((const float2*)(pvB + c));
                acc1[mf][nf][0] += h0.x; acc1[mf][nf][1] += h0.y;
                acc1[mf][nf][2] += h1.x; acc1[mf][nf][3] += h1.y;
            }
        }

        // ---- prefetch next tile's inputs into L2 ----
        {
            int nt = tile + gridDim.x;
            if (nt < N_TILES) {
                int nrow0 = nt * TILE_M;
                int r = tid >> 2, p = tid & 3;
                pref_l2((const char*)(paths + (size_t)(nrow0 + r) * 128) + p * 128);
                if (p == 0) pref_l2(Z_pat + (size_t)(nrow0 + r) * 32);
                if (tid < 2) pref_l2((const char*)(u + nrow0) + tid * 128);
            }
        }

        // ---- GN1 + ReLU -> xbuf (fp16) ----
        #pragma unroll
        for (int mf = 0; mf < 2; mf++)
            #pragma unroll
            for (int h = 0; h < 2; h++) {
                float s = 0.0f, ss = 0.0f;
                #pragma unroll
                for (int nf = 0; nf < 5; nf++) {
                    float a0 = acc1[mf][nf][2 * h], a1 = acc1[mf][nf][2 * h + 1];
                    s += a0 + a1; ss += a0 * a0 + a1 * a1;
                }
                s  += __shfl_xor_sync(0xffffffffu, s, 1);
                ss += __shfl_xor_sync(0xffffffffu, ss, 1);
                s  += __shfl_xor_sync(0xffffffffu, s, 2);
                ss += __shfl_xor_sync(0xffffffffu, ss, 2);
                if (qc == 0) {
                    int r = rb + mf * 16 + 8 * h;
                    atomicAdd(&rsum[r], s);
                    atomicAdd(&rssq[r], ss);
                }
            }
        __syncthreads();
        #pragma unroll
        for (int mf = 0; mf < 2; mf++)
            #pragma unroll
            for (int h = 0; h < 2; h++) {
                int r = rb + mf * 16 + 8 * h;
                float mean = rsum[r] * (1.0f / 160.0f);
                float var  = rssq[r] * (1.0f / 160.0f) - mean * mean;
                float rstd = rsqrtf(var + 1e-5f);
                #pragma unroll
                for (int nf = 0; nf < 5; nf++) {
                    int col = cb + nf * 8;
                    float v0 = fmaxf((acc1[mf][nf][2 * h]     - mean) * rstd * p1w[col]     + p1b[col],     0.f);
                    float v1 = fmaxf((acc1[mf][nf][2 * h + 1] - mean) * rstd * p1w[col + 1] + p1b[col + 1], 0.f);
                    *(unsigned*)(xbuf + r * XSB + col * 2) = h2u(v0, v1);
                }
            }
        __syncthreads();

        // ---- pass 2: h2 = h1r @ w2^T (B from smem), GN2, +tacc, ReLU, head ----
        {
            float acc[2][5][4] = {};
            {
                const char* bp = b2s + wn * 12800 + lane * 8;
                #pragma unroll
                for (int chunk = 0; chunk < 10; chunk++) {
                    uint2 b[5];
                    #pragma unroll
                    for (int j = 0; j < 5; j++)
                        b[j] = *(const uint2*)(bp + (chunk * 5 + j) * 256);
                    unsigned a[2][4];
                    uint32_t ad = xaddr0 + (uint32_t)(chunk * 32);
                    ldsm4(a[0], ad);
                    ldsm4(a[1], ad + 16 * XSB);
                    #pragma unroll
                    for (int mf = 0; mf < 2; mf++)
                        #pragma unroll
                        for (int nf = 0; nf < 5; nf++)
                            mma16(acc[mf][nf], a[mf], &b[nf].x);
                }
            }
            #pragma unroll
            for (int mf = 0; mf < 2; mf++)
                #pragma unroll
                for (int h = 0; h < 2; h++) {
                    float s = 0.0f, ss = 0.0f;
                    #pragma unroll
                    for (int nf = 0; nf < 5; nf++) {
                        float a0 = acc[mf][nf][2 * h], a1 = acc[mf][nf][2 * h + 1];
                        s += a0 + a1; ss += a0 * a0 + a1 * a1;
                    }
                    s  += __shfl_xor_sync(0xffffffffu, s, 1);
                    ss += __shfl_xor_sync(0xffffffffu, ss, 1);
                    s  += __shfl_xor_sync(0xffffffffu, s, 2);
                    ss += __shfl_xor_sync(0xffffffffu, ss, 2);
                    if (qc == 0) {
                        int r = rb + mf * 16 + 8 * h;
                        atomicAdd(&rsum2[r], s);
                        atomicAdd(&rssq2[r], ss);
                    }
                }
            __syncthreads();
            #pragma unroll
            for (int mf = 0; mf < 2; mf++)
                #pragma unroll
                for (int h = 0; h < 2; h++) {
                    int r = rb + mf * 16 + 8 * h;
                    float mean = rsum2[r] * (1.0f / 160.0f);
                    float var  = rssq2[r] * (1.0f / 160.0f) - mean * mean;
                    float rstd = rsqrtf(var + 1e-5f);
                    float part = 0.0f;
                    #pragma unroll
                    for (int nf = 0; nf < 5; nf++) {
                        int col = cb + nf * 8;
                        float v0 = (acc[mf][nf][2 * h]     - mean) * rstd * p2w[col]     + p2b[col]     + tacc[mf][nf][2 * h];
                        float v1 = (acc[mf][nf][2 * h + 1] - mean) * rstd * p2w[col + 1] + p2b[col + 1] + tacc[mf][nf][2 * h + 1];
                        v0 = fmaxf(v0, 0.0f);
                        v1 = fmaxf(v1, 0.0f);
                        part += v0 * pwh[col] + v1 * pwh[col + 1];
                    }
                    part += __shfl_xor_sync(0xffffffffu, part, 1);
                    part += __shfl_xor_sync(0xffffffffu, part, 2);
                    if (qc == 0) atomicAdd(&oacc[r], part);
                }
        }
        __syncthreads();
        // out store + stat re-zero for next tile (consumers all behind the barrier above)
        if (tid < TILE_M) {
            out[row0 + tid] = oacc[tid] + bhv;
            rsum[tid] = 0.0f; rssq[tid] = 0.0f;
            rsum2[tid] = 0.0f; rssq2[tid] = 0.0f; oacc[tid] = 0.0f;
        }
        __syncthreads();
    }
}

extern "C" void kernel_launch(void* const* d_in, const int* in_sizes, int n_in,
                              void* d_out, int out_size)
{
    const float* actors = (const float*)d_in[0];
    const float* paths  = (const float*)d_in[1];
    const float* Z_act  = (const float*)d_in[2];
    const float* Z_pat  = (const float*)d_in[3];
    const int*   u      = (const int*)  d_in[4];
    const float* w1     = (const float*)d_in[5];
    const float* w2     = (const float*)d_in[6];
    const float* wt     = (const float*)d_in[7];
    const float* g1w    = (const float*)d_in[8];
    const float* g1b    = (const float*)d_in[9];
    const float* g2w    = (const float*)d_in[10];
    const float* g2b    = (const float*)d_in[11];
    const float* wh     = (const float*)d_in[12];
    const float* bh     = (const float*)d_in[13];
    float* out = (float*)d_out;

    const int smem1 = VTILE * XSB;
    const int smem2 = TILE_M * XSB + 51200 + TILE_M * 4 + 5 * TILE_M * 4 + 5 * 160 * 4;

    static int nsm = 0;
    if (nsm == 0) {
        cudaDeviceProp prop;
        cudaGetDeviceProperties(&prop, 0);
        nsm = prop.multiProcessorCount;
        cudaFuncSetAttribute(veh_pre_kernel,   cudaFuncAttributeMaxDynamicSharedMemorySize, smem1);
        cudaFuncSetAttribute(path_main_kernel, cudaFuncAttributeMaxDynamicSharedMemorySize, smem2);
    }

    pack_kernel<<<(32000 + 255) / 256, 256>>>(w1, w2, wt);
    dim3 vgrid((N_VEH + VTILE - 1) / VTILE, 2);
    veh_pre_kernel<<<vgrid, VTHREADS, smem1>>>(actors, Z_act);
    path_main_kernel<<<2 * nsm, NTHREADS, smem2>>>(
        paths, Z_pat, u, g1w, g1b, g2w, g2b, wh, bh, out);
}